// round 6
// baseline (speedup 1.0000x reference)
#include <cuda_runtime.h>
#include <cstdint>
#include <cstddef>

typedef unsigned long long u64;
#define DEVINL __device__ __forceinline__

// ---------- packed f32x2 helpers ----------
DEVINL u64 dup2(float v) { u64 r; asm("mov.b64 %0, {%1, %1};" : "=l"(r) : "f"(v)); return r; }
DEVINL float2 u2f(u64 v) { float2 f; asm("mov.b64 {%0, %1}, %2;" : "=f"(f.x), "=f"(f.y) : "l"(v)); return f; }
DEVINL void fma2(u64& d, u64 a, u64 b) { asm("fma.rn.f32x2 %0, %1, %2, %0;" : "+l"(d) : "l"(a), "l"(b)); }
DEVINL u64 mul2(u64 a, u64 b) { u64 d; asm("mul.rn.f32x2 %0, %1, %2;" : "=l"(d) : "l"(a), "l"(b)); return d; }

DEVINL float red16max(float v) {
    v = fmaxf(v, __shfl_xor_sync(0xffffffffu, v, 1));
    v = fmaxf(v, __shfl_xor_sync(0xffffffffu, v, 2));
    v = fmaxf(v, __shfl_xor_sync(0xffffffffu, v, 4));
    v = fmaxf(v, __shfl_xor_sync(0xffffffffu, v, 8));
    return v;
}
DEVINL float red16sum(float v) {
    v += __shfl_xor_sync(0xffffffffu, v, 1);
    v += __shfl_xor_sync(0xffffffffu, v, 2);
    v += __shfl_xor_sync(0xffffffffu, v, 4);
    v += __shfl_xor_sync(0xffffffffu, v, 8);
    return v;
}

// B=8, C=512, N=1024 tokens, heads=4, d_k=128, M=8192 tokens total
__device__ float g_qkv[8192ull * 1536ull];   // [token][h*384 + {q:0,k:128,v:256} + d]
__device__ float g_attT[512ull * 8192ull];   // transposed attn out: [c = h*128+d][token]

// ============================================================================
// Kernel 1: qkv = xs @ Wp + bp.  xs[m][c] = x[b][c][pos] (x layout = A^T, free)
// 128x128x16 tiles, 256 thr, 8x8/thread split {ty*4, 64+ty*4} x {tx*4, 64+tx*4}
// ============================================================================
__global__ void __launch_bounds__(256) qkv_kernel(const float* __restrict__ x,
                                                  const float* __restrict__ Wp,
                                                  const float* __restrict__ bp) {
    __shared__ float As[16][128];
    __shared__ float Bs[16][128];
    const int tid = threadIdx.x;
    const int tx = tid & 15, ty = tid >> 4;
    const int m0 = blockIdx.y * 128;
    const int n0 = blockIdx.x * 128;
    const int b = m0 >> 10;
    const int pos0 = m0 & 1023;
    const float* xb = x + (size_t)b * (512 * 1024) + pos0;

    u64 acc[8][4];
#pragma unroll
    for (int i = 0; i < 8; i++)
#pragma unroll
        for (int j = 0; j < 4; j++) acc[i][j] = 0ull;

    for (int k0 = 0; k0 < 512; k0 += 16) {
        __syncthreads();
#pragma unroll
        for (int it = 0; it < 2; it++) {
            int slot = it * 256 + tid;
            int kk = slot >> 5, q4 = slot & 31;
            *(float4*)&As[kk][q4 * 4] = *(const float4*)(xb + (size_t)(k0 + kk) * 1024 + q4 * 4);
            *(float4*)&Bs[kk][q4 * 4] = *(const float4*)(Wp + (size_t)(k0 + kk) * 1536 + n0 + q4 * 4);
        }
        __syncthreads();
#pragma unroll
        for (int kk = 0; kk < 16; kk++) {
            float4 a0 = *(const float4*)&As[kk][ty * 4];
            float4 a1 = *(const float4*)&As[kk][64 + ty * 4];
            ulonglong2 b0 = *(const ulonglong2*)&Bs[kk][tx * 4];
            ulonglong2 b1 = *(const ulonglong2*)&Bs[kk][64 + tx * 4];
            float am[8] = {a0.x, a0.y, a0.z, a0.w, a1.x, a1.y, a1.z, a1.w};
#pragma unroll
            for (int i = 0; i < 8; i++) {
                u64 ad = dup2(am[i]);
                fma2(acc[i][0], ad, b0.x);
                fma2(acc[i][1], ad, b0.y);
                fma2(acc[i][2], ad, b1.x);
                fma2(acc[i][3], ad, b1.y);
            }
        }
    }
    float4 bias0 = *(const float4*)(bp + n0 + tx * 4);
    float4 bias1 = *(const float4*)(bp + n0 + 64 + tx * 4);
#pragma unroll
    for (int i = 0; i < 8; i++) {
        int m = m0 + ((i < 4) ? (ty * 4 + i) : (64 + ty * 4 + i - 4));
        float* orow = g_qkv + (size_t)m * 1536 + n0;
        float2 p0 = u2f(acc[i][0]), p1 = u2f(acc[i][1]);
        float2 p2 = u2f(acc[i][2]), p3 = u2f(acc[i][3]);
        *(float4*)(orow + tx * 4) =
            make_float4(p0.x + bias0.x, p0.y + bias0.y, p1.x + bias0.z, p1.y + bias0.w);
        *(float4*)(orow + 64 + tx * 4) =
            make_float4(p2.x + bias1.x, p2.y + bias1.y, p3.x + bias1.z, p3.y + bias1.w);
    }
}

// ============================================================================
// Kernel 2: flash attention per (b,h). 64 q x 64 k tiles, D=128, 256 threads.
// Q/K transposed+swizzled [d][64], V natural [64][128], P transposed [key][q].
// Output written transposed to g_attT[c][token] via float2 token pairs.
// ============================================================================
#define ATTN_SMEM (28672 * 4)

__global__ void __launch_bounds__(256, 1) attn_kernel() {
    extern __shared__ float sm[];
    float* Qs = sm;              // [128][64] swizzled: Qs[d*64 + (r ^ 2*(d>>2))]
    float* Ks = sm + 8192;       // [128][64] swizzled
    float* Vs = sm + 16384;      // [64][128] natural
    float* Ps = sm + 24576;      // [64][64]  swizzled: Ps[c*64 + (r ^ 2*(c>>2))]
    const int tid = threadIdx.x;
    const int tx = tid & 15, ty = tid >> 4;
    const int qt = blockIdx.x, h = blockIdx.y, b = blockIdx.z;
    const int tok0 = b * 1024 + qt * 64;
    const float scale = 0.08838834764831845f;  // 128^-0.5

#pragma unroll
    for (int it = 0; it < 8; it++) {
        int slot = it * 256 + tid;
        int row = slot >> 5, d4 = slot & 31;
        float4 qv = *(const float4*)(g_qkv + (size_t)(tok0 + row) * 1536 + h * 384 + d4 * 4);
        int sc = row ^ (d4 * 2);
        int base = d4 * 4 * 64;
        Qs[base + sc]       = qv.x * scale;
        Qs[base + 64 + sc]  = qv.y * scale;
        Qs[base + 128 + sc] = qv.z * scale;
        Qs[base + 192 + sc] = qv.w * scale;
    }

    u64 racc[4][4];
#pragma unroll
    for (int i = 0; i < 4; i++)
#pragma unroll
        for (int j = 0; j < 4; j++) racc[i][j] = 0ull;
    float rmax[4] = {-1e30f, -1e30f, -1e30f, -1e30f};
    float rsum[4] = {0.f, 0.f, 0.f, 0.f};

    for (int kt = 0; kt < 16; kt++) {
        __syncthreads();  // prev PV done (and Q ready on iter 0)
        const int kbase = b * 1024 + kt * 64;
#pragma unroll
        for (int it = 0; it < 8; it++) {
            int slot = it * 256 + tid;
            int row = slot >> 5, d4 = slot & 31;
            const float* src = g_qkv + (size_t)(kbase + row) * 1536 + h * 384 + d4 * 4;
            float4 kv = *(const float4*)(src + 128);
            float4 vv = *(const float4*)(src + 256);
            int sc = row ^ (d4 * 2);
            int base = d4 * 4 * 64;
            Ks[base + sc]       = kv.x;
            Ks[base + 64 + sc]  = kv.y;
            Ks[base + 128 + sc] = kv.z;
            Ks[base + 192 + sc] = kv.w;
            *(float4*)&Vs[row * 128 + d4 * 4] = vv;
        }
        __syncthreads();

        // S[64x64] = Q K^T (pre-scaled), 4 rows x 4 cols per thread
        u64 sp[4][2];
#pragma unroll
        for (int i = 0; i < 4; i++) { sp[i][0] = 0ull; sp[i][1] = 0ull; }
#pragma unroll 4
        for (int d = 0; d < 128; d++) {
            int g = (d >> 2) << 1;
            const float* qrow = Qs + d * 64;
            const float* krow = Ks + d * 64;
            float2 qa0 = *(const float2*)(qrow + ((2 * ty) ^ g));
            float2 qa1 = *(const float2*)(qrow + ((32 + 2 * ty) ^ g));
            u64 kb0 = *(const u64*)(krow + ((2 * tx) ^ g));
            u64 kb1 = *(const u64*)(krow + ((32 + 2 * tx) ^ g));
            u64 a;
            a = dup2(qa0.x); fma2(sp[0][0], a, kb0); fma2(sp[0][1], a, kb1);
            a = dup2(qa0.y); fma2(sp[1][0], a, kb0); fma2(sp[1][1], a, kb1);
            a = dup2(qa1.x); fma2(sp[2][0], a, kb0); fma2(sp[2][1], a, kb1);
            a = dup2(qa1.y); fma2(sp[3][0], a, kb0); fma2(sp[3][1], a, kb1);
        }

        // online softmax + write P transposed
        const int cols[4] = {2 * tx, 2 * tx + 1, 32 + 2 * tx, 33 + 2 * tx};
        const int rows[4] = {2 * ty, 2 * ty + 1, 32 + 2 * ty, 33 + 2 * ty};
#pragma unroll
        for (int i = 0; i < 4; i++) {
            float2 p0 = u2f(sp[i][0]), p1 = u2f(sp[i][1]);
            float s0 = p0.x, s1 = p0.y, s2 = p1.x, s3 = p1.y;
            float tmax = red16max(fmaxf(fmaxf(s0, s1), fmaxf(s2, s3)));
            float mnew = fmaxf(rmax[i], tmax);
            float corr = __expf(rmax[i] - mnew);
            rmax[i] = mnew;
            float e0 = __expf(s0 - mnew), e1 = __expf(s1 - mnew);
            float e2 = __expf(s2 - mnew), e3 = __expf(s3 - mnew);
            rsum[i] = rsum[i] * corr + red16sum(e0 + e1 + e2 + e3);
            u64 c2 = dup2(corr);
            racc[i][0] = mul2(racc[i][0], c2);
            racc[i][1] = mul2(racc[i][1], c2);
            racc[i][2] = mul2(racc[i][2], c2);
            racc[i][3] = mul2(racc[i][3], c2);
            int r = rows[i];
            Ps[cols[0] * 64 + (r ^ ((cols[0] >> 2) << 1))] = e0;
            Ps[cols[1] * 64 + (r ^ ((cols[1] >> 2) << 1))] = e1;
            Ps[cols[2] * 64 + (r ^ ((cols[2] >> 2) << 1))] = e2;
            Ps[cols[3] * 64 + (r ^ ((cols[3] >> 2) << 1))] = e3;
        }
        __syncthreads();

        // O[64x128] += P V
#pragma unroll 4
        for (int j = 0; j < 64; j++) {
            int g = (j >> 2) << 1;
            const float* prow = Ps + j * 64;
            float2 pa0 = *(const float2*)(prow + ((2 * ty) ^ g));
            float2 pa1 = *(const float2*)(prow + ((32 + 2 * ty) ^ g));
            ulonglong2 v0 = *(const ulonglong2*)&Vs[j * 128 + tx * 4];
            ulonglong2 v1 = *(const ulonglong2*)&Vs[j * 128 + 64 + tx * 4];
            u64 a;
            a = dup2(pa0.x); fma2(racc[0][0], a, v0.x); fma2(racc[0][1], a, v0.y);
                             fma2(racc[0][2], a, v1.x); fma2(racc[0][3], a, v1.y);
            a = dup2(pa0.y); fma2(racc[1][0], a, v0.x); fma2(racc[1][1], a, v0.y);
                             fma2(racc[1][2], a, v1.x); fma2(racc[1][3], a, v1.y);
            a = dup2(pa1.x); fma2(racc[2][0], a, v0.x); fma2(racc[2][1], a, v0.y);
                             fma2(racc[2][2], a, v1.x); fma2(racc[2][3], a, v1.y);
            a = dup2(pa1.y); fma2(racc[3][0], a, v0.x); fma2(racc[3][1], a, v0.y);
                             fma2(racc[3][2], a, v1.x); fma2(racc[3][3], a, v1.y);
        }
    }

    // normalize + write transposed: g_attT[(h*128+d)*8192 + token], float2 pairs
    float inv0 = 1.0f / rsum[0], inv1 = 1.0f / rsum[1];
    float inv2 = 1.0f / rsum[2], inv3 = 1.0f / rsum[3];
#pragma unroll
    for (int j = 0; j < 4; j++) {
        int d0 = (j < 2) ? (tx * 4 + j * 2) : (64 + tx * 4 + (j - 2) * 2);
        float2 a = u2f(racc[0][j]);  // row 2ty,    d0 / d0+1
        float2 c = u2f(racc[1][j]);  // row 2ty+1
        float2 e = u2f(racc[2][j]);  // row 32+2ty
        float2 f = u2f(racc[3][j]);  // row 33+2ty
        size_t base0 = (size_t)(h * 128 + d0) * 8192 + tok0;
        size_t base1 = base0 + 8192;
        *(float2*)(g_attT + base0 + 2 * ty)      = make_float2(a.x * inv0, c.x * inv1);
        *(float2*)(g_attT + base1 + 2 * ty)      = make_float2(a.y * inv0, c.y * inv1);
        *(float2*)(g_attT + base0 + 32 + 2 * ty) = make_float2(e.x * inv2, f.x * inv3);
        *(float2*)(g_attT + base1 + 32 + 2 * ty) = make_float2(e.y * inv2, f.y * inv3);
    }
}

// ============================================================================
// Kernel 3: out[b][c][pos] = (attn @ Wo)[m][c] + bo[c] + xs[m][c], computed as
// C^T[c][tok] so writes + residual loads (x[b][c][pos]) are coalesced.
// ============================================================================
__global__ void __launch_bounds__(256) out_kernel(const float* __restrict__ x,
                                                  const float* __restrict__ Wo,
                                                  const float* __restrict__ bo,
                                                  float* __restrict__ out) {
    __shared__ float As[16][128];  // Wo[k][c] slice (contiguous in c)
    __shared__ float Bs[16][128];  // g_attT[k][tok] slice (contiguous in tok)
    const int tid = threadIdx.x;
    const int tx = tid & 15, ty = tid >> 4;
    const int c0 = blockIdx.x * 128;
    const int m0 = blockIdx.y * 128;
    const int b = m0 >> 10;
    const int pos0 = m0 & 1023;

    u64 acc[8][4];
#pragma unroll
    for (int i = 0; i < 8; i++)
#pragma unroll
        for (int j = 0; j < 4; j++) acc[i][j] = 0ull;

    for (int k0 = 0; k0 < 512; k0 += 16) {
        __syncthreads();
#pragma unroll
        for (int it = 0; it < 2; it++) {
            int slot = it * 256 + tid;
            int kk = slot >> 5, q4 = slot & 31;
            *(float4*)&As[kk][q4 * 4] = *(const float4*)(Wo + (size_t)(k0 + kk) * 512 + c0 + q4 * 4);
            *(float4*)&Bs[kk][q4 * 4] = *(const float4*)(g_attT + (size_t)(k0 + kk) * 8192 + m0 + q4 * 4);
        }
        __syncthreads();
#pragma unroll
        for (int kk = 0; kk < 16; kk++) {
            float4 a0 = *(const float4*)&As[kk][ty * 4];
            float4 a1 = *(const float4*)&As[kk][64 + ty * 4];
            ulonglong2 b0 = *(const ulonglong2*)&Bs[kk][tx * 4];
            ulonglong2 b1 = *(const ulonglong2*)&Bs[kk][64 + tx * 4];
            float am[8] = {a0.x, a0.y, a0.z, a0.w, a1.x, a1.y, a1.z, a1.w};
#pragma unroll
            for (int i = 0; i < 8; i++) {
                u64 ad = dup2(am[i]);
                fma2(acc[i][0], ad, b0.x);
                fma2(acc[i][1], ad, b0.y);
                fma2(acc[i][2], ad, b1.x);
                fma2(acc[i][3], ad, b1.y);
            }
        }
    }
#pragma unroll
    for (int i = 0; i < 8; i++) {
        int c = c0 + ((i < 4) ? (ty * 4 + i) : (64 + ty * 4 + i - 4));
        float bb = bo[c];
        const float* xr = x + ((size_t)b * 512 + c) * 1024 + pos0;
        float* orow = out + ((size_t)b * 512 + c) * 1024 + pos0;
        float4 r0 = *(const float4*)(xr + tx * 4);
        float4 r1 = *(const float4*)(xr + 64 + tx * 4);
        float2 p0 = u2f(acc[i][0]), p1 = u2f(acc[i][1]);
        float2 p2 = u2f(acc[i][2]), p3 = u2f(acc[i][3]);
        *(float4*)(orow + tx * 4) =
            make_float4(p0.x + bb + r0.x, p0.y + bb + r0.y, p1.x + bb + r0.z, p1.y + bb + r0.w);
        *(float4*)(orow + 64 + tx * 4) =
            make_float4(p2.x + bb + r1.x, p2.y + bb + r1.y, p3.x + bb + r1.z, p3.y + bb + r1.w);
    }
}

extern "C" void kernel_launch(void* const* d_in, const int* in_sizes, int n_in,
                              void* d_out, int out_size) {
    const float* x  = (const float*)d_in[0];
    const float* Wp = (const float*)d_in[1];
    const float* bp = (const float*)d_in[2];
    const float* Wo = (const float*)d_in[3];
    const float* bo = (const float*)d_in[4];
    float* out = (float*)d_out;

    static bool attr_set = false;
    if (!attr_set) {
        cudaFuncSetAttribute(attn_kernel, cudaFuncAttributeMaxDynamicSharedMemorySize, ATTN_SMEM);
        attr_set = true;
    }

    qkv_kernel<<<dim3(12, 64), 256>>>(x, Wp, bp);
    attn_kernel<<<dim3(16, 4, 8), 256, ATTN_SMEM>>>();
    out_kernel<<<dim3(4, 64), 256>>>(x, Wo, bo, out);
}